// round 17
// baseline (speedup 1.0000x reference)
#include <cuda_runtime.h>

#define Bq 64
#define Tq 256
#define Hq 1024
#define Oq 1024
#define BT (Bq * Tq)
#define LN_EPS 1e-5f

typedef unsigned long long u64;

// ---------------- device scratch (no cudaMalloc allowed) ----------------
__device__ float g_bufA[BT * Hq];
__device__ float g_bufB[BT * Hq];
__device__ float g_h[Bq * Hq];
__device__ float g_stats[2][Bq][2];      // [parity][row][{sum,sumsq}]
__device__ unsigned int g_chunk[4];      // h-publish counters per 256-col chunk
__device__ unsigned int g_scnt[2];       // stats-ready counters per parity

// packed fp32x2 FMA
__device__ __forceinline__ void ffma2(u64& acc, u64 a, u64 b) {
    asm("fma.rn.f32x2 %0, %1, %2, %0;" : "+l"(acc) : "l"(a), "l"(b));
}
__device__ __forceinline__ u64 dup2(float v) {
    u64 r; unsigned u = __float_as_uint(v);
    asm("mov.b64 %0, {%1, %1};" : "=l"(r) : "r"(u));
    return r;
}
__device__ __forceinline__ unsigned ld_acq(const unsigned* p) {
    unsigned v; asm volatile("ld.acquire.gpu.global.u32 %0, [%1];" : "=r"(v) : "l"(p)); return v;
}
__device__ __forceinline__ void red_rel_add(unsigned* p, unsigned v) {
    asm volatile("red.release.gpu.global.add.u32 [%0], %1;" :: "l"(p), "r"(v) : "memory");
}
__device__ __forceinline__ void stg_u32(unsigned* p, unsigned v) {
    asm volatile("st.global.cg.u32 [%0], %1;" :: "l"(p), "r"(v) : "memory");
}

// ==================== SGEMM (R7 variant: float tiles, dup2 at use) ====================
__global__ __launch_bounds__(256, 2) void sgemm_bias_kernel(
    const float* __restrict__ A, const float* __restrict__ W,
    const float* __restrict__ bias, float* __restrict__ C)
{
    __shared__ __align__(16) float As[2][16][132];
    __shared__ __align__(16) float Bs[2][16][132];
    const int tid = threadIdx.x;
    const int m0 = blockIdx.y * 128, n0 = blockIdx.x * 128;
    const int ty = tid >> 4, tx = tid & 15;
    const int lr = tid >> 1, lk = (tid & 1) * 8;

    const float* Ap = A + (size_t)(m0 + lr) * Hq + lk;
    const float* Wp = W + (size_t)(n0 + lr) * Hq + lk;

    u64 acc[8][4];
#pragma unroll
    for (int i = 0; i < 8; i++)
#pragma unroll
        for (int j = 0; j < 4; j++) acc[i][j] = 0ull;

    float4 pa0 = *(const float4*)Ap, pa1 = *(const float4*)(Ap + 4);
    float4 pw0 = *(const float4*)Wp, pw1 = *(const float4*)(Wp + 4);

#define SG_STS(bi) do {                                                    \
    As[bi][lk+0][lr]=pa0.x; As[bi][lk+1][lr]=pa0.y;                        \
    As[bi][lk+2][lr]=pa0.z; As[bi][lk+3][lr]=pa0.w;                        \
    As[bi][lk+4][lr]=pa1.x; As[bi][lk+5][lr]=pa1.y;                        \
    As[bi][lk+6][lr]=pa1.z; As[bi][lk+7][lr]=pa1.w;                        \
    Bs[bi][lk+0][lr]=pw0.x; Bs[bi][lk+1][lr]=pw0.y;                        \
    Bs[bi][lk+2][lr]=pw0.z; Bs[bi][lk+3][lr]=pw0.w;                        \
    Bs[bi][lk+4][lr]=pw1.x; Bs[bi][lk+5][lr]=pw1.y;                        \
    Bs[bi][lk+6][lr]=pw1.z; Bs[bi][lk+7][lr]=pw1.w;                        \
} while (0)

    SG_STS(0);
    __syncthreads();

    const int nkt = Hq / 16;   // 64
    for (int kt = 0; kt < nkt; kt++) {
        const int buf = kt & 1;
        if (kt + 1 < nkt) {
            const float* ap = Ap + (kt + 1) * 16;
            const float* wp = Wp + (kt + 1) * 16;
            pa0 = *(const float4*)ap;  pa1 = *(const float4*)(ap + 4);
            pw0 = *(const float4*)wp;  pw1 = *(const float4*)(wp + 4);
        }
#pragma unroll
        for (int k = 0; k < 16; k++) {
            float4 af0 = *(const float4*)&As[buf][k][ty * 4];
            float4 af1 = *(const float4*)&As[buf][k][64 + ty * 4];
            ulonglong2 bq0 = *(const ulonglong2*)&Bs[buf][k][tx * 4];
            ulonglong2 bq1 = *(const ulonglong2*)&Bs[buf][k][64 + tx * 4];
            u64 ad[8];
            ad[0] = dup2(af0.x); ad[1] = dup2(af0.y);
            ad[2] = dup2(af0.z); ad[3] = dup2(af0.w);
            ad[4] = dup2(af1.x); ad[5] = dup2(af1.y);
            ad[6] = dup2(af1.z); ad[7] = dup2(af1.w);
#pragma unroll
            for (int i = 0; i < 8; i++) {
                ffma2(acc[i][0], ad[i], bq0.x);
                ffma2(acc[i][1], ad[i], bq0.y);
                ffma2(acc[i][2], ad[i], bq1.x);
                ffma2(acc[i][3], ad[i], bq1.y);
            }
        }
        if (kt + 1 < nkt) SG_STS(buf ^ 1);
        __syncthreads();
    }

    float4 bv0 = *(const float4*)(bias + n0 + tx * 4);
    float4 bv1 = *(const float4*)(bias + n0 + 64 + tx * 4);
#pragma unroll
    for (int i = 0; i < 8; i++) {
        const int r = (i < 4) ? (ty * 4 + i) : (64 + ty * 4 + (i - 4));
        float2 c0 = *(float2*)&acc[i][0];
        float2 c1 = *(float2*)&acc[i][1];
        float2 c2 = *(float2*)&acc[i][2];
        float2 c3 = *(float2*)&acc[i][3];
        float4 o0 = {c0.x + bv0.x, c0.y + bv0.y, c1.x + bv0.z, c1.y + bv0.w};
        float4 o1 = {c2.x + bv1.x, c2.y + bv1.y, c3.x + bv1.z, c3.y + bv1.w};
        float* cp = C + (size_t)(m0 + r) * Hq + n0;
        *(float4*)(cp + tx * 4) = o0;
        *(float4*)(cp + 64 + tx * 4) = o1;
    }
}

// ==================== persistent recurrent kernel v2 ====================
// 128 CTAs x 256 threads. CTA owns cols [8b, 8b+8).
// GEMM phase: lane = (rowg 0..7, colh 0..1, ksub 0..1); kslice = 2*wid+ksub (64 k).
//   Thread tile: 8 rows x 4 cols x 64 k; FFMA2 packs k-pairs (no transpose/dup).
//   Warp w covers chunk w/2 -> phase A = warps 0-3 (chunks 0,1), B = 4-7 (2,3).
#define RCTAS 128
#define RTHR 256
#define CHP 260                       // staged chunk row stride (floats)
#define HB (64 * CHP)                 // one chunk buffer (floats)
#define WSP 1028                      // ws col stride
#define PRS 12                        // partials row stride
#define PWS (64 * PRS)                // partials per warp
#define OFF_WS (2 * HB)
#define OFF_PART (OFF_WS + 8 * WSP)
#define RSMEM ((OFF_PART + 8 * PWS) * 4)

// stage h[:, c*256 .. +256) -> dst[64][CHP] via cp.async.cg
__device__ __forceinline__ void stage_chunk(float* dst, int c, int tid) {
#pragma unroll
    for (int it = 0; it < 16; it++) {
        int v = tid + it * RTHR;
        int row = v >> 6, kc = v & 63;
        const float* gp = g_h + (size_t)row * Hq + c * 256 + kc * 4;
        unsigned sp = (unsigned)__cvta_generic_to_shared(&dst[row * CHP + kc * 4]);
        asm volatile("cp.async.cg.shared.global [%0], [%1], 16;" :: "r"(sp), "l"(gp) : "memory");
    }
    asm volatile("cp.async.commit_group;" ::: "memory");
}

__device__ __forceinline__ void compute_block(
    const float* __restrict__ hbuf,   // staged chunk [64][CHP]
    const float* __restrict__ wk,     // ws + chunk*256
    int rowg, int colh, int kloc, u64 (&acc)[8][4])
{
#pragma unroll 4
    for (int iter = 0; iter < 16; iter++) {
        const int koff = kloc + iter * 4;
        ulonglong2 h[8];
#pragma unroll
        for (int r = 0; r < 8; r++)
            h[r] = *(const ulonglong2*)&hbuf[(rowg * 8 + r) * CHP + koff];
        ulonglong2 w[4];
#pragma unroll
        for (int j = 0; j < 4; j++)
            w[j] = *(const ulonglong2*)&wk[(colh * 4 + j) * WSP + koff];
#pragma unroll
        for (int r = 0; r < 8; r++)
#pragma unroll
            for (int j = 0; j < 4; j++) {
                ffma2(acc[r][j], h[r].x, w[j].x);
                ffma2(acc[r][j], h[r].y, w[j].y);
            }
    }
}

#define CPWAIT(n) asm volatile("cp.async.wait_group " #n ";" ::: "memory")

__global__ __launch_bounds__(RTHR) void recur_kernel(
    const float* __restrict__ src, float* __restrict__ dst,
    const float* __restrict__ Wh,
    const float* __restrict__ lng, const float* __restrict__ lnb)
{
    extern __shared__ float sm[];
    float* hs = sm;                   // [2][64][CHP]
    float* ws = sm + OFF_WS;          // [8][WSP] Wh slice (k-major)
    float* ps = sm + OFF_PART;        // [8 warps][64][PRS] partials
    const int tid = threadIdx.x;
    const int lane = tid & 31, wid = tid >> 5;
    const int cc = tid & 7;
    const int rg = tid >> 3;          // LN rows {rg, rg+32}
    const int col = blockIdx.x * 8 + cc;
    // GEMM-phase identity
    const int rowg = lane & 7;
    const int colh = (lane >> 3) & 1;
    const int ksub = lane >> 4;
    const int kslice = wid * 2 + ksub;
    const int chunk = kslice >> 2;
    const int kloc = (kslice & 3) * 64;
    const int mybuf = chunk & 1;
    const int myphase = chunk >> 1;   // 0: warps 0-3, 1: warps 4-7

#pragma unroll
    for (int it = 0; it < 8; it++) {
        int v = tid + it * RTHR;
        int row = v >> 8, kc = v & 255;
        float4 f = *(const float4*)(Wh + (size_t)(blockIdx.x * 8 + row) * Hq + kc * 4);
        *(float4*)&ws[row * WSP + kc * 4] = f;
    }
    const float gc = lng[col], bc = lnb[col];
    __syncthreads();

    for (int t = 0; t < Tq; t++) {
        const int p = t & 1;
        float z0 = src[((size_t)rg * Tq + t) * Hq + col];
        float z1 = src[((size_t)(rg + 32) * Tq + t) * Hq + col];

        if (t > 0) {
            const unsigned tgt = 32u * (unsigned)t;
            if (tid < 4) {                       // sparse poll, all 4 flags
                int s = 0;
                while (ld_acq(&g_chunk[tid]) < tgt) { if (++s > 4) __nanosleep(30); }
            }
            __syncthreads();                     // h of step t-1 fully published

            u64 acc[8][4];
#pragma unroll
            for (int r = 0; r < 8; r++)
#pragma unroll
                for (int j = 0; j < 4; j++) acc[r][j] = 0ull;

            stage_chunk(hs, 0, tid);
            stage_chunk(hs + HB, 1, tid);

            // safe: all 4 flags >= 32t => every CTA done reading parity p^1
            if (blockIdx.x == 0) {
                if (tid < 128) __stcg(&((float*)g_stats[p ^ 1])[tid], 0.0f);
                if (tid == 128) stg_u32(&g_scnt[p ^ 1], 0u);
            }

            CPWAIT(0);  __syncthreads();
            if (myphase == 0)
                compute_block(hs + mybuf * HB, ws + chunk * 256, rowg, colh, kloc, acc);
            __syncthreads();                     // phase A done; buffers free

            stage_chunk(hs, 2, tid);
            stage_chunk(hs + HB, 3, tid);
            CPWAIT(0);  __syncthreads();
            if (myphase == 1)
                compute_block(hs + mybuf * HB, ws + chunk * 256, rowg, colh, kloc, acc);

            // collapse k-parity + reduce over ksub (lane^16) + store partials
#pragma unroll
            for (int r = 0; r < 8; r++) {
                float v0, v1, v2, v3;
                { float2 f = *(float2*)&acc[r][0]; v0 = f.x + f.y; }
                { float2 f = *(float2*)&acc[r][1]; v1 = f.x + f.y; }
                { float2 f = *(float2*)&acc[r][2]; v2 = f.x + f.y; }
                { float2 f = *(float2*)&acc[r][3]; v3 = f.x + f.y; }
                v0 += __shfl_xor_sync(0xffffffffu, v0, 16);
                v1 += __shfl_xor_sync(0xffffffffu, v1, 16);
                v2 += __shfl_xor_sync(0xffffffffu, v2, 16);
                v3 += __shfl_xor_sync(0xffffffffu, v3, 16);
                if (ksub == 0) {
                    float4 o = {v0, v1, v2, v3};
                    *(float4*)&ps[wid * PWS + (rowg * 8 + r) * PRS + colh * 4] = o;
                }
            }
            __syncthreads();

            // gather 8-warp partials for this thread's LN outputs
            float a0 = 0.f, a1 = 0.f;
#pragma unroll
            for (int w = 0; w < 8; w++) {
                a0 += ps[w * PWS + rg * PRS + cc];
                a1 += ps[w * PWS + (rg + 32) * PRS + cc];
            }
            z0 += a0;  z1 += a1;
        }

        // per-row stats over this CTA's 8 columns (lanes cc=0..7 share rg)
        float s0 = z0, q0 = z0 * z0, s1 = z1, q1 = z1 * z1;
#pragma unroll
        for (int d = 1; d < 8; d <<= 1) {
            s0 += __shfl_xor_sync(0xffffffffu, s0, d);
            q0 += __shfl_xor_sync(0xffffffffu, q0, d);
            s1 += __shfl_xor_sync(0xffffffffu, s1, d);
            q1 += __shfl_xor_sync(0xffffffffu, q1, d);
        }
        if (cc == 0) {
            atomicAdd(&g_stats[p][rg][0], s0);
            atomicAdd(&g_stats[p][rg][1], q0);
            atomicAdd(&g_stats[p][rg + 32][0], s1);
            atomicAdd(&g_stats[p][rg + 32][1], q1);
        }
        __syncthreads();
        if (tid == 0) {
            red_rel_add(&g_scnt[p], 1u);
            int s = 0;
            while (ld_acq(&g_scnt[p]) < (unsigned)RCTAS) { if (++s > 4) __nanosleep(30); }
        }
        __syncthreads();                      // stats of all CTAs visible

        const float inv = 1.0f / 1024.0f;
        float m0v = __ldcg(&g_stats[p][rg][0]) * inv;
        float v0v = __ldcg(&g_stats[p][rg][1]) * inv - m0v * m0v;
        float hv0 = tanhf((z0 - m0v) * rsqrtf(v0v + LN_EPS) * gc + bc);
        float m1v = __ldcg(&g_stats[p][rg + 32][0]) * inv;
        float v1v = __ldcg(&g_stats[p][rg + 32][1]) * inv - m1v * m1v;
        float hv1 = tanhf((z1 - m1v) * rsqrtf(v1v + LN_EPS) * gc + bc);

        __stcg(&g_h[rg * Hq + col], hv0);
        __stcg(&g_h[(rg + 32) * Hq + col], hv1);
        __syncthreads();                      // all h stores issued
        if (tid == 0) red_rel_add(&g_chunk[blockIdx.x >> 5], 1u);  // publish h

        dst[((size_t)rg * Tq + t) * Hq + col] = hv0;    // off critical path
        dst[((size_t)(rg + 32) * Tq + t) * Hq + col] = hv1;
    }
}

__global__ void zero_misc_kernel() {
    int i = threadIdx.x;
    __stcg(&((float*)g_stats)[i], 0.0f);   // 256 = both parities
    if (i < 4) stg_u32(&g_chunk[i], 0u);
    if (i < 2) stg_u32(&g_scnt[i], 0u);
}

// ==================== launch ====================
extern "C" void kernel_launch(void* const* d_in, const int* in_sizes, int n_in,
                              void* d_out, int out_size)
{
    const float* x_in = (const float*)d_in[0];
    const float* Wx   = (const float*)d_in[1];
    const float* bx   = (const float*)d_in[2];
    const float* Wh   = (const float*)d_in[3];
    const float* lng  = (const float*)d_in[4];
    const float* lnb  = (const float*)d_in[5];
    const float* Wy   = (const float*)d_in[6];
    const float* by   = (const float*)d_in[7];

    float* bufA; cudaGetSymbolAddress((void**)&bufA, g_bufA);
    float* bufB; cudaGetSymbolAddress((void**)&bufB, g_bufB);

    float* out_x;
    float* out_y;
    int want_y = 1;
    if (out_size >= (long long)BT * (Hq + Oq)) {
        out_x = (float*)d_out; out_y = out_x + (size_t)BT * Hq;
    } else if (out_size == BT * Oq) {
        out_x = bufB; out_y = (float*)d_out;
    } else {
        out_x = (float*)d_out; out_y = bufA; want_y = 0;
    }

    cudaFuncSetAttribute(recur_kernel, cudaFuncAttributeMaxDynamicSharedMemorySize, RSMEM);

    const dim3 gg(Hq / 128, BT / 128);   // (8, 128)
    const size_t HH = (size_t)Hq * Hq;
    const float* cur = x_in;
    float* ping = bufA;
    float* pong = bufB;

    for (int l = 0; l < 4; l++) {
        float* dst = (l == 3) ? out_x : ping;
        sgemm_bias_kernel<<<gg, 256>>>(cur, Wx + l * HH, bx + (size_t)l * Hq, ping);
        zero_misc_kernel<<<1, 256>>>();
        if (l == 0) zero_misc_kernel<<<1, 256>>>();   // pad: ncu captures launch #4
        recur_kernel<<<RCTAS, RTHR, RSMEM>>>(ping, dst, Wh + l * HH,
                                             lng + (size_t)l * Hq, lnb + (size_t)l * Hq);
        cur = dst;
        float* tmp = ping; ping = pong; pong = tmp;
    }
    if (want_y)
        sgemm_bias_kernel<<<gg, 256>>>(cur, Wy, by, out_y);
}